// round 7
// baseline (speedup 1.0000x reference)
#include <cuda_runtime.h>
#include <math.h>
#include <stdint.h>

#define D_MODEL 512
#define N_HEADS 8
#define D_KK    64
#define D_FF    2048
#define T_SEQ   2048
#define B_BATCH 2
#define BT      (B_BATCH * T_SEQ)
#define BH      (B_BATCH * N_HEADS)

#define OUT_ELEMS  ((size_t)BT * D_MODEL)
#define ATTN_ELEMS ((size_t)BH * T_SEQ * T_SEQ)

#define EPI_BIAS   0
#define EPI_RELU   1
#define EPI_QKV    2

#define LOG2E 1.4426950408889634f

/* ---------------- scratch ------------------------------------------------- */
__device__ float g_q[BH * T_SEQ * D_KK];
__device__ float g_k[BH * T_SEQ * D_KK];
__device__ float g_v[BH * T_SEQ * D_KK];
__device__ float g_ctx[BT * D_MODEL];
__device__ float g_tmp[BT * D_MODEL];
__device__ float g_h[BT * D_MODEL];
__device__ float g_ffn1[BT * D_FF];
__device__ float g_invsum[(size_t)BH * T_SEQ];
__device__ float g_attn_scratch[BH * (size_t)T_SEQ * T_SEQ];

/* ---------------- helpers ------------------------------------------------- */
/* tf32 operand: HMMA reads the top bits; raw fp32 bits = RZ-truncated tf32. */
__device__ __forceinline__ uint32_t f2tf(float f) { return __float_as_uint(f); }

__device__ __forceinline__ float ex2(float x) {
    float r;
    asm("ex2.approx.f32 %0, %1;" : "=f"(r) : "f"(x));
    return r;
}
__device__ __forceinline__ void mma8(float c[4], uint32_t a0, uint32_t a1,
                                     uint32_t a2, uint32_t a3,
                                     uint32_t b0, uint32_t b1) {
    asm volatile(
        "mma.sync.aligned.m16n8k8.row.col.f32.tf32.tf32.f32 "
        "{%0,%1,%2,%3}, {%4,%5,%6,%7}, {%8,%9}, {%0,%1,%2,%3};"
        : "+f"(c[0]), "+f"(c[1]), "+f"(c[2]), "+f"(c[3])
        : "r"(a0), "r"(a1), "r"(a2), "r"(a3), "r"(b0), "r"(b1));
}
__device__ __forceinline__ void cp16(float* sdst, const float* gsrc) {
    uint32_t s = (uint32_t)__cvta_generic_to_shared(sdst);
    asm volatile("cp.async.cg.shared.global [%0], [%1], 16;" :: "r"(s), "l"(gsrc));
}
__device__ __forceinline__ float warp_sum(float v) {
    #pragma unroll
    for (int o = 16; o > 0; o >>= 1) v += __shfl_xor_sync(0xffffffffu, v, o);
    return v;
}

/* ---------------- cp.async double-buffered tf32 GEMM --------------------- */
template <int BM, int EPI>
__global__ __launch_bounds__(256) void mma_gemm(
    const float* __restrict__ A,
    const float* __restrict__ B0, const float* __restrict__ B1, const float* __restrict__ B2,
    const float* __restrict__ bias0, const float* __restrict__ bias1, const float* __restrict__ bias2,
    float* __restrict__ C0, float* __restrict__ C1, float* __restrict__ C2,
    int M, int N, int K, int lda, int ldb, int ldc)
{
    constexpr int KT  = 32;
    constexpr int SA  = KT + 4;                  /* 36  */
    constexpr int SBk = 128 + 8;                 /* 136 */
    constexpr int A_ELE = BM * SA;
    constexpr int B_ELE = KT * SBk;
    constexpr int STG = A_ELE + B_ELE;
    constexpr int AN = (BM == 128) ? 8 : 4;

    extern __shared__ float smem[];

    const int tid = threadIdx.x;
    const int lane = tid & 31, wid = tid >> 5;
    const int z = blockIdx.z;
    const float* B    = (z == 0) ? B0 : (z == 1) ? B1 : B2;
    const float* bias = (z == 0) ? bias0 : (z == 1) ? bias1 : bias2;
    float* C          = (z == 0) ? C0 : (z == 1) ? C1 : C2;

    const int bm = blockIdx.y * BM;
    const int bn = blockIdx.x * 128;
    const int mb = (BM == 128) ? (wid & 3) * 32 : (wid & 1) * 32;
    const int nb = (BM == 128) ? (wid >> 2) * 64 : (wid >> 1) * 32;

    float acc[2][AN][4];
    #pragma unroll
    for (int i = 0; i < 2; i++)
        #pragma unroll
        for (int j = 0; j < AN; j++)
            #pragma unroll
            for (int r = 0; r < 4; r++) acc[i][j][r] = 0.0f;

    auto issue = [&](int k0, int st) {
        float* As = smem + st * STG;
        float* Bs = As + A_ELE;
        #pragma unroll
        for (int i = 0; i < BM * KT / 1024; i++) {
            int f = tid + i * 256;
            int m = f >> 3, k4 = (f & 7) * 4;
            cp16(&As[m * SA + k4], &A[(size_t)(bm + m) * lda + k0 + k4]);
        }
        #pragma unroll
        for (int i = 0; i < 4; i++) {
            int f = tid + i * 256;
            int kk = f >> 5, n4 = (f & 31) * 4;
            cp16(&Bs[kk * SBk + n4], &B[(size_t)(k0 + kk) * ldb + bn + n4]);
        }
        asm volatile("cp.async.commit_group;" ::: "memory");
    };

    issue(0, 0);
    const int nIter = K / KT;
    for (int it = 0; it < nIter; it++) {
        if (it + 1 < nIter) {
            issue((it + 1) * KT, (it + 1) & 1);
            asm volatile("cp.async.wait_group 1;" ::: "memory");
        } else {
            asm volatile("cp.async.wait_group 0;" ::: "memory");
        }
        __syncthreads();

        float* As = smem + (it & 1) * STG;
        float* Bs = As + A_ELE;
        #pragma unroll
        for (int ks = 0; ks < KT / 8; ks++) {
            uint32_t af[2][4], bf[AN][2];
            #pragma unroll
            for (int am = 0; am < 2; am++)
                #pragma unroll
                for (int j = 0; j < 4; j++)
                    af[am][j] = f2tf(As[(mb + am * 16 + (lane >> 2) + (j & 1) * 8) * SA
                                        + ks * 8 + (lane & 3) + (j >> 1) * 4]);
            #pragma unroll
            for (int an = 0; an < AN; an++)
                #pragma unroll
                for (int j = 0; j < 2; j++)
                    bf[an][j] = f2tf(Bs[(ks * 8 + (lane & 3) + j * 4) * SBk
                                        + nb + an * 8 + (lane >> 2)]);
            #pragma unroll
            for (int am = 0; am < 2; am++)
                #pragma unroll
                for (int an = 0; an < AN; an++)
                    mma8(acc[am][an], af[am][0], af[am][1], af[am][2], af[am][3],
                         bf[an][0], bf[an][1]);
        }
        __syncthreads();
    }

    #pragma unroll
    for (int am = 0; am < 2; am++)
        #pragma unroll
        for (int an = 0; an < AN; an++)
            #pragma unroll
            for (int half = 0; half < 2; half++) {
                int m = bm + mb + am * 16 + (lane >> 2) + half * 8;
                int c = bn + nb + an * 8 + (lane & 3) * 2;
                float v0 = acc[am][an][half * 2 + 0] + bias[c];
                float v1 = acc[am][an][half * 2 + 1] + bias[c + 1];
                if (EPI == EPI_RELU) { v0 = fmaxf(v0, 0.0f); v1 = fmaxf(v1, 0.0f); }
                if (EPI == EPI_QKV) {
                    int bb = m >> 11, t = m & (T_SEQ - 1);
                    int h = c >> 6, d = c & (D_KK - 1);
                    *(float2*)&C[((size_t)((bb * N_HEADS + h) * T_SEQ) + t) * D_KK + d]
                        = make_float2(v0, v1);
                } else {
                    *(float2*)&C[(size_t)m * ldc + c] = make_float2(v0, v1);
                }
            }
}

/* ---------------- rowsum: inv[row] = 1 / sum_n exp2(S*sc) -----------------
 * CTA owns a 64-row stripe; loops all 32 K-tiles. No attn traffic.
 */
__global__ __launch_bounds__(256, 3) void rowsum_kernel(
    const float* __restrict__ Q, const float* __restrict__ K,
    float* __restrict__ inv)
{
    constexpr int S = 68;
    extern __shared__ float sm[];
    float* Qs  = sm;                 /* 64*68 */
    float* Ks0 = sm + 64 * S;        /* 2 stages of 64*68 */
    float* rs  = sm + 3 * 64 * S;    /* 64 */

    const int tid = threadIdx.x;
    const int lane = tid & 31, wid = tid >> 5;
    const int z = blockIdx.y;
    const int bm = blockIdx.x * 64;
    Q += (size_t)z * T_SEQ * D_KK;
    K += (size_t)z * T_SEQ * D_KK;

    if (tid < 64) rs[tid] = 0.0f;

    /* Q stripe */
    #pragma unroll
    for (int i = 0; i < 4; i++) {
        int f = tid + i * 256;
        int m = f >> 4, k4 = (f & 15) * 4;
        cp16(&Qs[m * S + k4], &Q[(size_t)(bm + m) * D_KK + k4]);
    }
    auto issueK = [&](int it, int st) {
        float* Ks = Ks0 + st * 64 * S;
        #pragma unroll
        for (int i = 0; i < 4; i++) {
            int f = tid + i * 256;
            int n = f >> 4, k4 = (f & 15) * 4;
            cp16(&Ks[n * S + k4], &K[(size_t)(it * 64 + n) * D_KK + k4]);
        }
        asm volatile("cp.async.commit_group;" ::: "memory");
    };
    issueK(0, 0);

    const int mb = (wid & 1) * 32;
    const int nb = (wid >> 1) * 16;
    const float sc = 0.125f * LOG2E;

    float rsum[2][2] = {{0.0f, 0.0f}, {0.0f, 0.0f}};

    for (int it = 0; it < 32; it++) {
        if (it + 1 < 32) {
            issueK(it + 1, (it + 1) & 1);
            asm volatile("cp.async.wait_group 1;" ::: "memory");
        } else {
            asm volatile("cp.async.wait_group 0;" ::: "memory");
        }
        __syncthreads();

        float* Ks = Ks0 + (it & 1) * 64 * S;
        float acc[2][2][4];
        #pragma unroll
        for (int i = 0; i < 2; i++)
            #pragma unroll
            for (int j = 0; j < 2; j++)
                #pragma unroll
                for (int r = 0; r < 4; r++) acc[i][j][r] = 0.0f;

        #pragma unroll
        for (int ks = 0; ks < 8; ks++) {
            uint32_t af[2][4], bf[2][2];
            #pragma unroll
            for (int am = 0; am < 2; am++)
                #pragma unroll
                for (int j = 0; j < 4; j++)
                    af[am][j] = f2tf(Qs[(mb + am * 16 + (lane >> 2) + (j & 1) * 8) * S
                                        + ks * 8 + (lane & 3) + (j >> 1) * 4]);
            #pragma unroll
            for (int an = 0; an < 2; an++)
                #pragma unroll
                for (int j = 0; j < 2; j++)
                    bf[an][j] = f2tf(Ks[(nb + an * 8 + (lane >> 2)) * S
                                        + ks * 8 + (lane & 3) + j * 4]);
            #pragma unroll
            for (int am = 0; am < 2; am++)
                #pragma unroll
                for (int an = 0; an < 2; an++)
                    mma8(acc[am][an], af[am][0], af[am][1], af[am][2], af[am][3],
                         bf[an][0], bf[an][1]);
        }
        #pragma unroll
        for (int am = 0; am < 2; am++)
            #pragma unroll
            for (int an = 0; an < 2; an++)
                #pragma unroll
                for (int r = 0; r < 4; r++)
                    rsum[am][r >> 1] += ex2(acc[am][an][r] * sc);
        __syncthreads();
    }

    #pragma unroll
    for (int am = 0; am < 2; am++)
        #pragma unroll
        for (int h = 0; h < 2; h++) {
            float v = rsum[am][h];
            v += __shfl_xor_sync(0xffffffffu, v, 1);
            v += __shfl_xor_sync(0xffffffffu, v, 2);
            if ((lane & 3) == 0)
                atomicAdd(&rs[mb + am * 16 + (lane >> 2) + h * 8], v);
        }
    __syncthreads();
    if (tid < 64)
        inv[(size_t)z * T_SEQ + bm + tid] = 1.0f / rs[tid];
}

/* ---------------- fused scores-recompute + attn write + P@V --------------
 * CTA owns a 64-row stripe. Per K/V tile: recompute S, P=exp2(S*sc)*inv to
 * smem, write normalized attn tile (write-only), P@V from the same smem.
 */
__global__ __launch_bounds__(256, 2) void attn_pv2_kernel(
    const float* __restrict__ Q, const float* __restrict__ K,
    const float* __restrict__ V, const float* __restrict__ inv,
    float* __restrict__ attn, float* __restrict__ ctx)
{
    constexpr int S  = 68;
    constexpr int SV = 72;
    constexpr int K_ELE = 64 * S;    /* 4352 */
    constexpr int V_ELE = 64 * SV;   /* 4608 */
    constexpr int STG = K_ELE + V_ELE;
    extern __shared__ float sm[];
    float* Qs   = sm;                       /* 64*68 */
    float* St0  = sm + K_ELE;               /* 2 stages {Ks, Vs} */
    float* Ps   = sm + K_ELE + 2 * STG;     /* 64*68 */
    float* invs = Ps + K_ELE;               /* 64 */

    const int tid = threadIdx.x;
    const int lane = tid & 31, wid = tid >> 5;
    const int z = blockIdx.y;
    const int bm = blockIdx.x * 64;
    Q    += (size_t)z * T_SEQ * D_KK;
    K    += (size_t)z * T_SEQ * D_KK;
    V    += (size_t)z * T_SEQ * D_KK;
    attn += (size_t)z * T_SEQ * T_SEQ;

    #pragma unroll
    for (int i = 0; i < 4; i++) {
        int f = tid + i * 256;
        int m = f >> 4, k4 = (f & 15) * 4;
        cp16(&Qs[m * S + k4], &Q[(size_t)(bm + m) * D_KK + k4]);
    }
    auto issueKV = [&](int it, int st) {
        float* Ks = St0 + st * STG;
        float* Vs = Ks + K_ELE;
        #pragma unroll
        for (int i = 0; i < 4; i++) {
            int f = tid + i * 256;
            int n = f >> 4, k4 = (f & 15) * 4;
            cp16(&Ks[n * S + k4], &K[(size_t)(it * 64 + n) * D_KK + k4]);
        }
        #pragma unroll
        for (int i = 0; i < 4; i++) {
            int f = tid + i * 256;
            int kk = f >> 4, c4 = (f & 15) * 4;
            cp16(&Vs[kk * SV + c4], &V[(size_t)(it * 64 + kk) * D_KK + c4]);
        }
        asm volatile("cp.async.commit_group;" ::: "memory");
    };
    issueKV(0, 0);
    if (tid < 64) invs[tid] = inv[(size_t)z * T_SEQ + bm + tid];
    __syncthreads();

    const int mb = (wid & 1) * 32;
    const int nb = (wid >> 1) * 16;
    const float sc = 0.125f * LOG2E;

    /* per-thread row inverses (rows fixed across the loop) */
    float iv[2][2];
    #pragma unroll
    for (int am = 0; am < 2; am++)
        #pragma unroll
        for (int h = 0; h < 2; h++)
            iv[am][h] = invs[mb + am * 16 + (lane >> 2) + h * 8];

    float acc2[2][2][4];
    #pragma unroll
    for (int i = 0; i < 2; i++)
        #pragma unroll
        for (int j = 0; j < 2; j++)
            #pragma unroll
            for (int r = 0; r < 4; r++) acc2[i][j][r] = 0.0f;

    for (int it = 0; it < 32; it++) {
        if (it + 1 < 32) {
            issueKV(it + 1, (it + 1) & 1);
            asm volatile("cp.async.wait_group 1;" ::: "memory");
        } else {
            asm volatile("cp.async.wait_group 0;" ::: "memory");
        }
        __syncthreads();

        float* Ks = St0 + (it & 1) * STG;
        float* Vs = Ks + K_ELE;

        /* S = Q @ K^T */
        float sacc[2][2][4];
        #pragma unroll
        for (int i = 0; i < 2; i++)
            #pragma unroll
            for (int j = 0; j < 2; j++)
                #pragma unroll
                for (int r = 0; r < 4; r++) sacc[i][j][r] = 0.0f;
        #pragma unroll
        for (int ks = 0; ks < 8; ks++) {
            uint32_t af[2][4], bf[2][2];
            #pragma unroll
            for (int am = 0; am < 2; am++)
                #pragma unroll
                for (int j = 0; j < 4; j++)
                    af[am][j] = f2tf(Qs[(mb + am * 16 + (lane >> 2) + (j & 1) * 8) * S
                                        + ks * 8 + (lane & 3) + (j >> 1) * 4]);
            #pragma unroll
            for (int an = 0; an < 2; an++)
                #pragma unroll
                for (int j = 0; j < 2; j++)
                    bf[an][j] = f2tf(Ks[(nb + an * 8 + (lane >> 2)) * S
                                        + ks * 8 + (lane & 3) + j * 4]);
            #pragma unroll
            for (int am = 0; am < 2; am++)
                #pragma unroll
                for (int an = 0; an < 2; an++)
                    mma8(sacc[am][an], af[am][0], af[am][1], af[am][2], af[am][3],
                         bf[an][0], bf[an][1]);
        }

        /* P = exp2(S*sc) * inv -> smem */
        #pragma unroll
        for (int am = 0; am < 2; am++)
            #pragma unroll
            for (int an = 0; an < 2; an++)
                #pragma unroll
                for (int h = 0; h < 2; h++) {
                    int row = mb + am * 16 + (lane >> 2) + h * 8;
                    int c = nb + an * 8 + (lane & 3) * 2;
                    float e0 = ex2(sacc[am][an][h * 2 + 0] * sc) * iv[am][h];
                    float e1 = ex2(sacc[am][an][h * 2 + 1] * sc) * iv[am][h];
                    *(float2*)&Ps[row * S + c] = make_float2(e0, e1);
                }
        __syncthreads();

        /* normalized attn tile: write-only, coalesced */
        #pragma unroll
        for (int i = 0; i < 4; i++) {
            int f = tid + i * 256;
            int m = f >> 4, k4 = (f & 15) * 4;
            float4 v = *(const float4*)&Ps[m * S + k4];
            *(float4*)&attn[(size_t)(bm + m) * T_SEQ + it * 64 + k4] = v;
        }

        /* ctx += P @ V */
        #pragma unroll
        for (int ks = 0; ks < 8; ks++) {
            uint32_t af[2][4], bf[2][2];
            #pragma unroll
            for (int am = 0; am < 2; am++)
                #pragma unroll
                for (int j = 0; j < 4; j++)
                    af[am][j] = f2tf(Ps[(mb + am * 16 + (lane >> 2) + (j & 1) * 8) * S
                                        + ks * 8 + (lane & 3) + (j >> 1) * 4]);
            #pragma unroll
            for (int an = 0; an < 2; an++)
                #pragma unroll
                for (int j = 0; j < 2; j++)
                    bf[an][j] = f2tf(Vs[(ks * 8 + (lane & 3) + j * 4) * SV
                                        + nb + an * 8 + (lane >> 2)]);
            #pragma unroll
            for (int am = 0; am < 2; am++)
                #pragma unroll
                for (int an = 0; an < 2; an++)
                    mma8(acc2[am][an], af[am][0], af[am][1], af[am][2], af[am][3],
                         bf[an][0], bf[an][1]);
        }
        __syncthreads();
    }

    const int b = z >> 3, h = z & 7;
    float* Cz = ctx + (size_t)b * T_SEQ * D_MODEL + h * D_KK;
    #pragma unroll
    for (int am = 0; am < 2; am++)
        #pragma unroll
        for (int an = 0; an < 2; an++)
            #pragma unroll
            for (int half = 0; half < 2; half++) {
                int mr = bm + mb + am * 16 + (lane >> 2) + half * 8;
                int c = nb + an * 8 + (lane & 3) * 2;
                *(float2*)&Cz[(size_t)mr * D_MODEL + c]
                    = make_float2(acc2[am][an][half * 2 + 0],
                                  acc2[am][an][half * 2 + 1]);
            }
}

/* ---------------- fused residual add + LayerNorm ------------------------- */
__global__ __launch_bounds__(128) void add_ln_kernel(
    const float* __restrict__ X, const float* __restrict__ Y,
    const float* __restrict__ g, const float* __restrict__ b,
    float* __restrict__ O)
{
    const int tid = threadIdx.x;
    const size_t base = (size_t)blockIdx.x * D_MODEL + tid * 4;
    float4 xv = *(const float4*)&X[base];
    float4 yv = *(const float4*)&Y[base];
    float4 v = make_float4(xv.x + yv.x, xv.y + yv.y, xv.z + yv.z, xv.w + yv.w);

    float s  = v.x + v.y + v.z + v.w;
    float ss = v.x * v.x + v.y * v.y + v.z * v.z + v.w * v.w;
    s = warp_sum(s);
    ss = warp_sum(ss);

    __shared__ float r1[4], r2[4];
    const int wid = tid >> 5, lane = tid & 31;
    if (lane == 0) { r1[wid] = s; r2[wid] = ss; }
    __syncthreads();
    if (tid == 0) {
        float a = 0.0f, c = 0.0f;
        #pragma unroll
        for (int i = 0; i < 4; i++) { a += r1[i]; c += r2[i]; }
        r1[0] = a; r2[0] = c;
    }
    __syncthreads();
    const float mu  = r1[0] * (1.0f / 512.0f);
    const float var = r2[0] * (1.0f / 512.0f) - mu * mu;
    const float rs  = rsqrtf(var + 1e-5f);

    float4 gv = *(const float4*)&g[tid * 4];
    float4 bv = *(const float4*)&b[tid * 4];
    float4 o;
    o.x = (v.x - mu) * rs * gv.x + bv.x;
    o.y = (v.y - mu) * rs * gv.y + bv.y;
    o.z = (v.z - mu) * rs * gv.z + bv.z;
    o.w = (v.w - mu) * rs * gv.w + bv.w;
    *(float4*)&O[base] = o;
}

/* ---------------- launch -------------------------------------------------- */
#define SMEM_G128   71680   /* 2*(128*36 + 32*136)*4 */
#define SMEM_G64    53248   /* 2*( 64*36 + 32*136)*4 */
#define SMEM_RS     52480   /* (3*64*68 + 64)*4 */
#define SMEM_PV2    106752  /* (64*68 + 2*(64*68+64*72) + 64*68 + 64)*4 */

extern "C" void kernel_launch(void* const* d_in, const int* in_sizes, int n_in,
                              void* d_out, int out_size)
{
    const float* x     = (const float*)d_in[0];
    const float* wq_w  = (const float*)d_in[1];
    const float* wq_b  = (const float*)d_in[2];
    const float* wk_w  = (const float*)d_in[3];
    const float* wk_b  = (const float*)d_in[4];
    const float* wv_w  = (const float*)d_in[5];
    const float* wv_b  = (const float*)d_in[6];
    const float* wo_w  = (const float*)d_in[7];
    const float* wo_b  = (const float*)d_in[8];
    const float* ln1_g = (const float*)d_in[9];
    const float* ln1_b = (const float*)d_in[10];
    const float* fc1_w = (const float*)d_in[11];
    const float* fc1_b = (const float*)d_in[12];
    const float* fc2_w = (const float*)d_in[13];
    const float* fc2_b = (const float*)d_in[14];
    const float* ln2_g = (const float*)d_in[15];
    const float* ln2_b = (const float*)d_in[16];

    float* out = (float*)d_out;

    float *pq, *pk, *pv, *pctx, *ptmp, *ph, *pffn1, *pinv;
    cudaGetSymbolAddress((void**)&pq,    g_q);
    cudaGetSymbolAddress((void**)&pk,    g_k);
    cudaGetSymbolAddress((void**)&pv,    g_v);
    cudaGetSymbolAddress((void**)&pctx,  g_ctx);
    cudaGetSymbolAddress((void**)&ptmp,  g_tmp);
    cudaGetSymbolAddress((void**)&ph,    g_h);
    cudaGetSymbolAddress((void**)&pffn1, g_ffn1);
    cudaGetSymbolAddress((void**)&pinv,  g_invsum);

    float* attn;
    if ((size_t)out_size >= OUT_ELEMS + ATTN_ELEMS) {
        attn = out + OUT_ELEMS;
    } else {
        cudaGetSymbolAddress((void**)&attn, g_attn_scratch);
    }

    cudaFuncSetAttribute(mma_gemm<128, EPI_QKV>,
                         cudaFuncAttributeMaxDynamicSharedMemorySize, SMEM_G128);
    cudaFuncSetAttribute(mma_gemm<128, EPI_BIAS>,
                         cudaFuncAttributeMaxDynamicSharedMemorySize, SMEM_G128);
    cudaFuncSetAttribute(mma_gemm<128, EPI_RELU>,
                         cudaFuncAttributeMaxDynamicSharedMemorySize, SMEM_G128);
    cudaFuncSetAttribute(mma_gemm<64, EPI_BIAS>,
                         cudaFuncAttributeMaxDynamicSharedMemorySize, SMEM_G64);
    cudaFuncSetAttribute(rowsum_kernel,
                         cudaFuncAttributeMaxDynamicSharedMemorySize, SMEM_RS);
    cudaFuncSetAttribute(attn_pv2_kernel,
                         cudaFuncAttributeMaxDynamicSharedMemorySize, SMEM_PV2);

    /* QKV: one launch, z selects weight/bias/output */
    mma_gemm<128, EPI_QKV><<<dim3(4, 32, 3), 256, SMEM_G128>>>(
        x, wq_w, wk_w, wv_w, wq_b, wk_b, wv_b, pq, pk, pv,
        BT, D_MODEL, D_MODEL, D_MODEL, D_MODEL, D_MODEL);

    /* rowsum -> inv (no attn traffic) */
    rowsum_kernel<<<dim3(T_SEQ / 64, BH), 256, SMEM_RS>>>(pq, pk, pinv);

    /* recompute scores, write normalized attn (write-only), ctx = P @ V */
    attn_pv2_kernel<<<dim3(T_SEQ / 64, BH), 256, SMEM_PV2>>>(
        pq, pk, pv, pinv, attn, pctx);

    /* output projection + LN1 */
    mma_gemm<128, EPI_BIAS><<<dim3(4, 32, 1), 256, SMEM_G128>>>(
        pctx, wo_w, wo_w, wo_w, wo_b, wo_b, wo_b, ptmp, ptmp, ptmp,
        BT, D_MODEL, D_MODEL, D_MODEL, D_MODEL, D_MODEL);
    add_ln_kernel<<<BT, 128>>>(x, ptmp, ln1_g, ln1_b, ph);

    /* FFN + LN2 */
    mma_gemm<128, EPI_RELU><<<dim3(16, 32, 1), 256, SMEM_G128>>>(
        ph, fc1_w, fc1_w, fc1_w, fc1_b, fc1_b, fc1_b, pffn1, pffn1, pffn1,
        BT, D_FF, D_MODEL, D_MODEL, D_FF, D_FF);
    mma_gemm<64, EPI_BIAS><<<dim3(4, 64, 1), 256, SMEM_G64>>>(
        pffn1, fc2_w, fc2_w, fc2_w, fc2_b, fc2_b, fc2_b, ptmp, ptmp, ptmp,
        BT, D_MODEL, D_FF, D_FF, D_MODEL, D_MODEL);
    add_ln_kernel<<<BT, 128>>>(ph, ptmp, ln2_g, ln2_b, out);
}

// round 8
// speedup vs baseline: 1.1456x; 1.1456x over previous
#include <cuda_runtime.h>
#include <math.h>
#include <stdint.h>

#define D_MODEL 512
#define N_HEADS 8
#define D_KK    64
#define D_FF    2048
#define T_SEQ   2048
#define B_BATCH 2
#define BT      (B_BATCH * T_SEQ)
#define BH      (B_BATCH * N_HEADS)

#define OUT_ELEMS  ((size_t)BT * D_MODEL)
#define ATTN_ELEMS ((size_t)BH * T_SEQ * T_SEQ)

#define EPI_BIAS   0
#define EPI_RELU   1
#define EPI_QKV    2

#define LOG2E 1.4426950408889634f

/* ---------------- scratch ------------------------------------------------- */
__device__ float g_q[BH * T_SEQ * D_KK];
__device__ float g_k[BH * T_SEQ * D_KK];
__device__ float g_v[BH * T_SEQ * D_KK];
__device__ float g_ctx[BT * D_MODEL];
__device__ float g_tmp[BT * D_MODEL];
__device__ float g_h[BT * D_MODEL];
__device__ float g_ffn1[BT * D_FF];
__device__ float g_psum[(size_t)BH * T_SEQ * 32];
__device__ float g_attn_scratch[BH * (size_t)T_SEQ * T_SEQ];

/* ---------------- helpers ------------------------------------------------- */
/* tf32 operand: HMMA reads the top bits; raw fp32 bits = RZ-truncated tf32. */
__device__ __forceinline__ uint32_t f2tf(float f) { return __float_as_uint(f); }

__device__ __forceinline__ float ex2(float x) {
    float r;
    asm("ex2.approx.f32 %0, %1;" : "=f"(r) : "f"(x));
    return r;
}
__device__ __forceinline__ void mma8(float c[4], uint32_t a0, uint32_t a1,
                                     uint32_t a2, uint32_t a3,
                                     uint32_t b0, uint32_t b1) {
    asm volatile(
        "mma.sync.aligned.m16n8k8.row.col.f32.tf32.tf32.f32 "
        "{%0,%1,%2,%3}, {%4,%5,%6,%7}, {%8,%9}, {%0,%1,%2,%3};"
        : "+f"(c[0]), "+f"(c[1]), "+f"(c[2]), "+f"(c[3])
        : "r"(a0), "r"(a1), "r"(a2), "r"(a3), "r"(b0), "r"(b1));
}
__device__ __forceinline__ void cp16(float* sdst, const float* gsrc) {
    uint32_t s = (uint32_t)__cvta_generic_to_shared(sdst);
    asm volatile("cp.async.cg.shared.global [%0], [%1], 16;" :: "r"(s), "l"(gsrc));
}
__device__ __forceinline__ float warp_sum(float v) {
    #pragma unroll
    for (int o = 16; o > 0; o >>= 1) v += __shfl_xor_sync(0xffffffffu, v, o);
    return v;
}

/* ---------------- cp.async double-buffered tf32 GEMM --------------------- */
template <int BM, int EPI>
__global__ __launch_bounds__(256) void mma_gemm(
    const float* __restrict__ A,
    const float* __restrict__ B0, const float* __restrict__ B1, const float* __restrict__ B2,
    const float* __restrict__ bias0, const float* __restrict__ bias1, const float* __restrict__ bias2,
    float* __restrict__ C0, float* __restrict__ C1, float* __restrict__ C2,
    int M, int N, int K, int lda, int ldb, int ldc)
{
    constexpr int KT  = 32;
    constexpr int SA  = KT + 4;                  /* 36  */
    constexpr int SBk = 128 + 8;                 /* 136 */
    constexpr int A_ELE = BM * SA;
    constexpr int B_ELE = KT * SBk;
    constexpr int STG = A_ELE + B_ELE;
    constexpr int AN = (BM == 128) ? 8 : 4;

    extern __shared__ float smem[];

    const int tid = threadIdx.x;
    const int lane = tid & 31, wid = tid >> 5;
    const int z = blockIdx.z;
    const float* B    = (z == 0) ? B0 : (z == 1) ? B1 : B2;
    const float* bias = (z == 0) ? bias0 : (z == 1) ? bias1 : bias2;
    float* C          = (z == 0) ? C0 : (z == 1) ? C1 : C2;

    const int bm = blockIdx.y * BM;
    const int bn = blockIdx.x * 128;
    const int mb = (BM == 128) ? (wid & 3) * 32 : (wid & 1) * 32;
    const int nb = (BM == 128) ? (wid >> 2) * 64 : (wid >> 1) * 32;

    float acc[2][AN][4];
    #pragma unroll
    for (int i = 0; i < 2; i++)
        #pragma unroll
        for (int j = 0; j < AN; j++)
            #pragma unroll
            for (int r = 0; r < 4; r++) acc[i][j][r] = 0.0f;

    auto issue = [&](int k0, int st) {
        float* As = smem + st * STG;
        float* Bs = As + A_ELE;
        #pragma unroll
        for (int i = 0; i < BM * KT / 1024; i++) {
            int f = tid + i * 256;
            int m = f >> 3, k4 = (f & 7) * 4;
            cp16(&As[m * SA + k4], &A[(size_t)(bm + m) * lda + k0 + k4]);
        }
        #pragma unroll
        for (int i = 0; i < 4; i++) {
            int f = tid + i * 256;
            int kk = f >> 5, n4 = (f & 31) * 4;
            cp16(&Bs[kk * SBk + n4], &B[(size_t)(k0 + kk) * ldb + bn + n4]);
        }
        asm volatile("cp.async.commit_group;" ::: "memory");
    };

    issue(0, 0);
    const int nIter = K / KT;
    for (int it = 0; it < nIter; it++) {
        if (it + 1 < nIter) {
            issue((it + 1) * KT, (it + 1) & 1);
            asm volatile("cp.async.wait_group 1;" ::: "memory");
        } else {
            asm volatile("cp.async.wait_group 0;" ::: "memory");
        }
        __syncthreads();

        float* As = smem + (it & 1) * STG;
        float* Bs = As + A_ELE;
        #pragma unroll
        for (int ks = 0; ks < KT / 8; ks++) {
            uint32_t af[2][4], bf[AN][2];
            #pragma unroll
            for (int am = 0; am < 2; am++)
                #pragma unroll
                for (int j = 0; j < 4; j++)
                    af[am][j] = f2tf(As[(mb + am * 16 + (lane >> 2) + (j & 1) * 8) * SA
                                        + ks * 8 + (lane & 3) + (j >> 1) * 4]);
            #pragma unroll
            for (int an = 0; an < AN; an++)
                #pragma unroll
                for (int j = 0; j < 2; j++)
                    bf[an][j] = f2tf(Bs[(ks * 8 + (lane & 3) + j * 4) * SBk
                                        + nb + an * 8 + (lane >> 2)]);
            #pragma unroll
            for (int am = 0; am < 2; am++)
                #pragma unroll
                for (int an = 0; an < AN; an++)
                    mma8(acc[am][an], af[am][0], af[am][1], af[am][2], af[am][3],
                         bf[an][0], bf[an][1]);
        }
        __syncthreads();
    }

    #pragma unroll
    for (int am = 0; am < 2; am++)
        #pragma unroll
        for (int an = 0; an < AN; an++)
            #pragma unroll
            for (int half = 0; half < 2; half++) {
                int m = bm + mb + am * 16 + (lane >> 2) + half * 8;
                int c = bn + nb + an * 8 + (lane & 3) * 2;
                float v0 = acc[am][an][half * 2 + 0] + bias[c];
                float v1 = acc[am][an][half * 2 + 1] + bias[c + 1];
                if (EPI == EPI_RELU) { v0 = fmaxf(v0, 0.0f); v1 = fmaxf(v1, 0.0f); }
                if (EPI == EPI_QKV) {
                    int bb = m >> 11, t = m & (T_SEQ - 1);
                    int h = c >> 6, d = c & (D_KK - 1);
                    *(float2*)&C[((size_t)((bb * N_HEADS + h) * T_SEQ) + t) * D_KK + d]
                        = make_float2(v0, v1);
                } else {
                    *(float2*)&C[(size_t)m * ldc + c] = make_float2(v0, v1);
                }
            }
}

/* ---------------- scores: attn <- exp2(QK^T * sc), partial row sums -------
 * 128 x 128 tile, K=64 one-shot, exp evaluated ONCE here.
 */
__global__ __launch_bounds__(256) void scores_kernel(
    const float* __restrict__ Q, const float* __restrict__ K,
    float* __restrict__ attn, float* __restrict__ psum)
{
    constexpr int S = 68;
    extern __shared__ float sm[];
    float* Qs = sm;              /* [128][68] */
    float* Ks = sm + 128 * S;    /* [128][68] */

    const int tid = threadIdx.x;
    const int lane = tid & 31, wid = tid >> 5;
    const int z = blockIdx.z;
    const int bm = blockIdx.y * 128;
    const int bn = blockIdx.x * 128;
    Q += (size_t)z * T_SEQ * D_KK;
    K += (size_t)z * T_SEQ * D_KK;

    #pragma unroll
    for (int i = 0; i < 8; i++) {
        int f = tid + i * 256;
        int m = f >> 4, k4 = (f & 15) * 4;
        cp16(&Qs[m * S + k4], &Q[(size_t)(bm + m) * D_KK + k4]);
        cp16(&Ks[m * S + k4], &K[(size_t)(bn + m) * D_KK + k4]);
    }
    asm volatile("cp.async.commit_group;" ::: "memory");
    asm volatile("cp.async.wait_group 0;" ::: "memory");
    __syncthreads();

    const int mb = (wid & 3) * 32;
    const int nwarp = wid >> 2;
    const int nb = nwarp * 64;

    float acc[2][8][4];
    #pragma unroll
    for (int i = 0; i < 2; i++)
        #pragma unroll
        for (int j = 0; j < 8; j++)
            #pragma unroll
            for (int r = 0; r < 4; r++) acc[i][j][r] = 0.0f;

    #pragma unroll
    for (int ks = 0; ks < 8; ks++) {
        uint32_t af[2][4], bf[8][2];
        #pragma unroll
        for (int am = 0; am < 2; am++)
            #pragma unroll
            for (int j = 0; j < 4; j++)
                af[am][j] = f2tf(Qs[(mb + am * 16 + (lane >> 2) + (j & 1) * 8) * S
                                    + ks * 8 + (lane & 3) + (j >> 1) * 4]);
        #pragma unroll
        for (int an = 0; an < 8; an++)
            #pragma unroll
            for (int j = 0; j < 2; j++)
                bf[an][j] = f2tf(Ks[(nb + an * 8 + (lane >> 2)) * S
                                    + ks * 8 + (lane & 3) + j * 4]);
        #pragma unroll
        for (int am = 0; am < 2; am++)
            #pragma unroll
            for (int an = 0; an < 8; an++)
                mma8(acc[am][an], af[am][0], af[am][1], af[am][2], af[am][3],
                     bf[an][0], bf[an][1]);
    }

    const float sc = 0.125f * LOG2E;
    float* Cz = attn + (size_t)z * T_SEQ * T_SEQ;
    #pragma unroll
    for (int am = 0; am < 2; am++)
        #pragma unroll
        for (int half = 0; half < 2; half++) {
            int m = bm + mb + am * 16 + (lane >> 2) + half * 8;
            float rs = 0.0f;
            #pragma unroll
            for (int an = 0; an < 8; an++) {
                int c = bn + nb + an * 8 + (lane & 3) * 2;
                float e0 = ex2(acc[am][an][half * 2 + 0] * sc);
                float e1 = ex2(acc[am][an][half * 2 + 1] * sc);
                *(float2*)&Cz[(size_t)m * T_SEQ + c] = make_float2(e0, e1);
                rs += e0 + e1;
            }
            rs += __shfl_xor_sync(0xffffffffu, rs, 1);
            rs += __shfl_xor_sync(0xffffffffu, rs, 2);
            if ((lane & 3) == 0)
                psum[((size_t)z * T_SEQ + m) * 32 + blockIdx.x * 2 + nwarp] = rs;
        }
}

/* ---------------- fused psum-reduce + normalize + attn write + P@V --------
 * BM=64 stripe per CTA (exclusive owner of its rows -> reduces own psums).
 */
__global__ __launch_bounds__(256, 3) void attn_pv_kernel(
    float* __restrict__ attn, const float* __restrict__ V,
    const float* __restrict__ psum, float* __restrict__ ctx)
{
    constexpr int KT = 64;
    constexpr int BM = 64;
    constexpr int SA = 68;     /* [m=64][k=64]+4 */
    constexpr int SV = 72;     /* [k=64][n=64]+8 */
    constexpr int A_ELE = BM * SA;             /* 4352 */
    constexpr int STG = A_ELE + KT * SV;       /* 8960 */
    extern __shared__ float sm[];
    float* invs = sm + 2 * STG;

    const int tid = threadIdx.x;
    const int lane = tid & 31, wid = tid >> 5;
    const int bm = blockIdx.x * BM;
    const int z = blockIdx.y;
    attn += (size_t)z * T_SEQ * T_SEQ;
    V    += (size_t)z * T_SEQ * D_KK;

    auto issue = [&](int k0, int st) {
        float* As = sm + st * STG;
        float* Vs = As + A_ELE;
        #pragma unroll
        for (int i = 0; i < 4; i++) {
            int f = tid + i * 256;
            int m = f >> 4, k4 = (f & 15) * 4;
            cp16(&As[m * SA + k4], &attn[(size_t)(bm + m) * T_SEQ + k0 + k4]);
        }
        #pragma unroll
        for (int i = 0; i < 4; i++) {
            int f = tid + i * 256;
            int kk = f >> 4, c4 = (f & 15) * 4;
            cp16(&Vs[kk * SV + c4], &V[(size_t)(k0 + kk) * D_KK + c4]);
        }
        asm volatile("cp.async.commit_group;" ::: "memory");
    };

    issue(0, 0);

    /* reduce this stripe's psums -> invs (CTA exclusively owns rows) */
    if (tid < BM) {
        const float4* p = (const float4*)(psum + ((size_t)z * T_SEQ + bm + tid) * 32);
        float s = 0.0f;
        #pragma unroll
        for (int i = 0; i < 8; i++) {
            float4 v = p[i];
            s += v.x + v.y + v.z + v.w;
        }
        invs[tid] = 1.0f / s;
    }
    __syncthreads();

    const int mb = (wid & 1) * 32;
    const int nb = (wid >> 1) * 16;

    float acc[2][2][4];
    #pragma unroll
    for (int i = 0; i < 2; i++)
        #pragma unroll
        for (int j = 0; j < 2; j++)
            #pragma unroll
            for (int r = 0; r < 4; r++) acc[i][j][r] = 0.0f;

    const int nIter = T_SEQ / KT;   /* 32 */
    for (int it = 0; it < nIter; it++) {
        if (it + 1 < nIter) {
            issue((it + 1) * KT, (it + 1) & 1);
            asm volatile("cp.async.wait_group 1;" ::: "memory");
        } else {
            asm volatile("cp.async.wait_group 0;" ::: "memory");
        }
        __syncthreads();

        float* As = sm + (it & 1) * STG;
        float* Vs = As + A_ELE;

        #pragma unroll
        for (int ks = 0; ks < KT / 8; ks++) {
            uint32_t af[2][4], bf[2][2];
            #pragma unroll
            for (int am = 0; am < 2; am++)
                #pragma unroll
                for (int j = 0; j < 4; j++)
                    af[am][j] = f2tf(As[(mb + am * 16 + (lane >> 2) + (j & 1) * 8) * SA
                                        + ks * 8 + (lane & 3) + (j >> 1) * 4]);
            #pragma unroll
            for (int an = 0; an < 2; an++)
                #pragma unroll
                for (int j = 0; j < 2; j++)
                    bf[an][j] = f2tf(Vs[(ks * 8 + (lane & 3) + j * 4) * SV
                                        + nb + an * 8 + (lane >> 2)]);
            #pragma unroll
            for (int am = 0; am < 2; am++)
                #pragma unroll
                for (int an = 0; an < 2; an++)
                    mma8(acc[am][an], af[am][0], af[am][1], af[am][2], af[am][3],
                         bf[an][0], bf[an][1]);
        }

        /* normalized in-place attn write from smem (coalesced STG.128) */
        #pragma unroll
        for (int i = 0; i < 4; i++) {
            int f = tid + i * 256;
            int m = f >> 4, k4 = (f & 15) * 4;
            float4 v = *(const float4*)&As[m * SA + k4];
            float iv = invs[m];
            v.x *= iv; v.y *= iv; v.z *= iv; v.w *= iv;
            *(float4*)&attn[(size_t)(bm + m) * T_SEQ + it * KT + k4] = v;
        }
        __syncthreads();
    }

    const int b = z >> 3, h = z & 7;
    float* Cz = ctx + (size_t)b * T_SEQ * D_MODEL + h * D_KK;
    #pragma unroll
    for (int am = 0; am < 2; am++)
        #pragma unroll
        for (int an = 0; an < 2; an++)
            #pragma unroll
            for (int half = 0; half < 2; half++) {
                int mr = mb + am * 16 + (lane >> 2) + half * 8;
                int c = nb + an * 8 + (lane & 3) * 2;
                float iv = invs[mr];
                *(float2*)&Cz[(size_t)(bm + mr) * D_MODEL + c]
                    = make_float2(acc[am][an][half * 2 + 0] * iv,
                                  acc[am][an][half * 2 + 1] * iv);
            }
}

/* ---------------- fused residual add + LayerNorm ------------------------- */
__global__ __launch_bounds__(128) void add_ln_kernel(
    const float* __restrict__ X, const float* __restrict__ Y,
    const float* __restrict__ g, const float* __restrict__ b,
    float* __restrict__ O)
{
    const int tid = threadIdx.x;
    const size_t base = (size_t)blockIdx.x * D_MODEL + tid * 4;
    float4 xv = *(const float4*)&X[base];
    float4 yv = *(const float4*)&Y[base];
    float4 v = make_float4(xv.x + yv.x, xv.y + yv.y, xv.z + yv.z, xv.w + yv.w);

    float s  = v.x + v.y + v.z + v.w;
    float ss = v.x * v.x + v.y * v.y + v.z * v.z + v.w * v.w;
    s = warp_sum(s);
    ss = warp_sum(ss);

    __shared__ float r1[4], r2[4];
    const int wid = tid >> 5, lane = tid & 31;
    if (lane == 0) { r1[wid] = s; r2[wid] = ss; }
    __syncthreads();
    if (tid == 0) {
        float a = 0.0f, c = 0.0f;
        #pragma unroll
        for (int i = 0; i < 4; i++) { a += r1[i]; c += r2[i]; }
        r1[0] = a; r2[0] = c;
    }
    __syncthreads();
    const float mu  = r1[0] * (1.0f / 512.0f);
    const float var = r2[0] * (1.0f / 512.0f) - mu * mu;
    const float rs  = rsqrtf(var + 1e-5f);

    float4 gv = *(const float4*)&g[tid * 4];
    float4 bv = *(const float4*)&b[tid * 4];
    float4 o;
    o.x = (v.x - mu) * rs * gv.x + bv.x;
    o.y = (v.y - mu) * rs * gv.y + bv.y;
    o.z = (v.z - mu) * rs * gv.z + bv.z;
    o.w = (v.w - mu) * rs * gv.w + bv.w;
    *(float4*)&O[base] = o;
}

/* ---------------- launch -------------------------------------------------- */
#define SMEM_G128   71680   /* 2*(128*36 + 32*136)*4 */
#define SMEM_G64    53248   /* 2*( 64*36 + 32*136)*4 */
#define SMEM_SCORES 69632   /* 2*128*68*4 */
#define SMEM_PV     71936   /* (2*8960 + 64)*4 */

extern "C" void kernel_launch(void* const* d_in, const int* in_sizes, int n_in,
                              void* d_out, int out_size)
{
    const float* x     = (const float*)d_in[0];
    const float* wq_w  = (const float*)d_in[1];
    const float* wq_b  = (const float*)d_in[2];
    const float* wk_w  = (const float*)d_in[3];
    const float* wk_b  = (const float*)d_in[4];
    const float* wv_w  = (const float*)d_in[5];
    const float* wv_b  = (const float*)d_in[6];
    const float* wo_w  = (const float*)d_in[7];
    const float* wo_b  = (const float*)d_in[8];
    const float* ln1_g = (const float*)d_in[9];
    const float* ln1_b = (const float*)d_in[10];
    const float* fc1_w = (const float*)d_in[11];
    const float* fc1_b = (const float*)d_in[12];
    const float* fc2_w = (const float*)d_in[13];
    const float* fc2_b = (const float*)d_in[14];
    const float* ln2_g = (const float*)d_in[15];
    const float* ln2_b = (const float*)d_in[16];

    float* out = (float*)d_out;

    float *pq, *pk, *pv, *pctx, *ptmp, *ph, *pffn1, *ppsum;
    cudaGetSymbolAddress((void**)&pq,    g_q);
    cudaGetSymbolAddress((void**)&pk,    g_k);
    cudaGetSymbolAddress((void**)&pv,    g_v);
    cudaGetSymbolAddress((void**)&pctx,  g_ctx);
    cudaGetSymbolAddress((void**)&ptmp,  g_tmp);
    cudaGetSymbolAddress((void**)&ph,    g_h);
    cudaGetSymbolAddress((void**)&pffn1, g_ffn1);
    cudaGetSymbolAddress((void**)&ppsum, g_psum);

    float* attn;
    if ((size_t)out_size >= OUT_ELEMS + ATTN_ELEMS) {
        attn = out + OUT_ELEMS;
    } else {
        cudaGetSymbolAddress((void**)&attn, g_attn_scratch);
    }

    cudaFuncSetAttribute(mma_gemm<64, EPI_QKV>,
                         cudaFuncAttributeMaxDynamicSharedMemorySize, SMEM_G64);
    cudaFuncSetAttribute(mma_gemm<64, EPI_BIAS>,
                         cudaFuncAttributeMaxDynamicSharedMemorySize, SMEM_G64);
    cudaFuncSetAttribute(mma_gemm<128, EPI_RELU>,
                         cudaFuncAttributeMaxDynamicSharedMemorySize, SMEM_G128);
    cudaFuncSetAttribute(scores_kernel,
                         cudaFuncAttributeMaxDynamicSharedMemorySize, SMEM_SCORES);
    cudaFuncSetAttribute(attn_pv_kernel,
                         cudaFuncAttributeMaxDynamicSharedMemorySize, SMEM_PV);

    /* QKV: one launch, BM=64 (grid 768 -> 2-3 CTAs/SM) */
    mma_gemm<64, EPI_QKV><<<dim3(4, 64, 3), 256, SMEM_G64>>>(
        x, wq_w, wk_w, wv_w, wq_b, wk_b, wv_b, pq, pk, pv,
        BT, D_MODEL, D_MODEL, D_MODEL, D_MODEL, D_MODEL);

    /* scores + exp (once) + partial row sums; 128x128 tiles */
    scores_kernel<<<dim3(16, 16, BH), 256, SMEM_SCORES>>>(pq, pk, attn, ppsum);

    /* psum reduce + normalize attn in place + ctx = P @ V */
    attn_pv_kernel<<<dim3(T_SEQ / 64, BH), 256, SMEM_PV>>>(attn, pv, ppsum, pctx);

    /* output projection (BM=64, grid 256) + LN1 */
    mma_gemm<64, EPI_BIAS><<<dim3(4, 64, 1), 256, SMEM_G64>>>(
        pctx, wo_w, wo_w, wo_w, wo_b, wo_b, wo_b, ptmp, ptmp, ptmp,
        BT, D_MODEL, D_MODEL, D_MODEL, D_MODEL, D_MODEL);
    add_ln_kernel<<<BT, 128>>>(x, ptmp, ln1_g, ln1_b, ph);

    /* FFN + LN2 */
    mma_gemm<128, EPI_RELU><<<dim3(16, 32, 1), 256, SMEM_G128>>>(
        ph, fc1_w, fc1_w, fc1_w, fc1_b, fc1_b, fc1_b, pffn1, pffn1, pffn1,
        BT, D_FF, D_MODEL, D_MODEL, D_FF, D_FF);
    mma_gemm<64, EPI_BIAS><<<dim3(4, 64, 1), 256, SMEM_G64>>>(
        pffn1, fc2_w, fc2_w, fc2_w, fc2_b, fc2_b, fc2_b, ptmp, ptmp, ptmp,
        BT, D_MODEL, D_FF, D_FF, D_MODEL, D_MODEL);
    add_ln_kernel<<<BT, 128>>>(ph, ptmp, ln2_g, ln2_b, out);
}